// round 1
// baseline (speedup 1.0000x reference)
#include <cuda_runtime.h>
#include <cuda_bf16.h>
#include <math.h>

// Problem constants
#define SEQ   4096        // n = 64*64
#define NHEAD 8
#define DHEAD 64

// Scratch (static device allocations are the sanctioned workaround)
__device__ float g_qkv[1536 * SEQ];   // [3*8*64][4096] : q,k,v stacked
__device__ float g_att[512 * SEQ];    // [8*64][4096]   : attention output

// ---------------------------------------------------------------------------
// Generic fp32 GEMM: C[M,N] = A[M,K] (row-major) * B[K,N] (row-major) (+bias)
// BM=128, BN=64, BK=16; 256 threads; 8x4 register tile per thread.
// ---------------------------------------------------------------------------
__global__ void __launch_bounds__(256) gemm128x64(
    const float* __restrict__ A, const float* __restrict__ B,
    const float* __restrict__ bias, float* __restrict__ C,
    int M, int N, int K)
{
    __shared__ __align__(16) float As[16][128];
    __shared__ __align__(16) float Bs[16][64];

    const int tid = threadIdx.x;
    const int ty = tid >> 4, tx = tid & 15;
    const int m0 = blockIdx.y * 128, n0 = blockIdx.x * 64;

    float acc[8][4] = {};

    for (int k0 = 0; k0 < K; k0 += 16) {
        // Load A tile (128x16), transposed into As[k][m]
        #pragma unroll
        for (int i = 0; i < 2; i++) {
            int f = tid + i * 256;          // 0..511 float4 slots
            int r = f >> 2;                 // 0..127
            int kq = (f & 3) * 4;           // 0,4,8,12
            float4 av = *(const float4*)(A + (size_t)(m0 + r) * K + k0 + kq);
            As[kq + 0][r] = av.x; As[kq + 1][r] = av.y;
            As[kq + 2][r] = av.z; As[kq + 3][r] = av.w;
        }
        // Load B tile (16x64)
        {
            int kk = tid >> 4, n4 = (tid & 15) * 4;
            *(float4*)&Bs[kk][n4] =
                *(const float4*)(B + (size_t)(k0 + kk) * N + n0 + n4);
        }
        __syncthreads();

        #pragma unroll
        for (int kk = 0; kk < 16; kk++) {
            float4 a0 = *(float4*)&As[kk][ty * 8];
            float4 a1 = *(float4*)&As[kk][ty * 8 + 4];
            float4 b  = *(float4*)&Bs[kk][tx * 4];
            float ar[8] = {a0.x, a0.y, a0.z, a0.w, a1.x, a1.y, a1.z, a1.w};
            float br[4] = {b.x, b.y, b.z, b.w};
            #pragma unroll
            for (int a = 0; a < 8; a++)
                #pragma unroll
                for (int c = 0; c < 4; c++)
                    acc[a][c] = fmaf(ar[a], br[c], acc[a][c]);
        }
        __syncthreads();
    }

    #pragma unroll
    for (int a = 0; a < 8; a++) {
        int row = m0 + ty * 8 + a;
        float bb = bias ? bias[row] : 0.0f;
        float4 o = {acc[a][0] + bb, acc[a][1] + bb, acc[a][2] + bb, acc[a][3] + bb};
        *(float4*)(C + (size_t)row * N + n0 + tx * 4) = o;
    }
}

// ---------------------------------------------------------------------------
// Flash attention, fp32. One CTA per (head, 128-row i-tile).
// q,k,v stored d-major: q[h][d][i] = qkv[(h*64+d)*SEQ + i], etc.
// TI = TJ = 128. 256 threads: ty=tid/16 owns 8 i-rows, tx=tid%16 owns
// 8 j-cols (strided, j = tx + 16*b) for S, and 4 d-cols (d = tx*4..) for O.
// ---------------------------------------------------------------------------
__global__ void __launch_bounds__(256, 1) flash_kernel(
    const float* __restrict__ qkv, float* __restrict__ out)
{
    extern __shared__ float sm[];
    float* Qs = sm;                       // [64][128]   d-major
    float* Ks = sm + 64 * 128;            // [64][128]   d-major
    float* Vt = sm + 2 * 64 * 128;        // [128][68]   j-major (transposed)
    float* Ps = Vt + 128 * 68;            // [128][132]

    const int tid = threadIdx.x;
    const int ty = tid >> 4, tx = tid & 15;
    const int h = blockIdx.y;
    const int i0 = blockIdx.x * 128;

    const float* q = g_qkv + (size_t)(h * 64) * SEQ;
    const float* k = g_qkv + (size_t)(512 + h * 64) * SEQ;
    const float* v = g_qkv + (size_t)(1024 + h * 64) * SEQ;
    (void)qkv;

    const float scale = 0.125f;  // 64^-0.5

    // Load Q tile (pre-scaled)
    #pragma unroll
    for (int f = tid; f < 64 * 32; f += 256) {
        int d = f >> 5, j4 = (f & 31) * 4;
        float4 qv = *(const float4*)(q + (size_t)d * SEQ + i0 + j4);
        qv.x *= scale; qv.y *= scale; qv.z *= scale; qv.w *= scale;
        *(float4*)&Qs[d * 128 + j4] = qv;
    }

    float o[8][4] = {};
    float mrow[8], lrow[8];
    #pragma unroll
    for (int a = 0; a < 8; a++) { mrow[a] = -1e30f; lrow[a] = 0.0f; }

    for (int jt = 0; jt < 32; jt++) {
        const int j0 = jt * 128;
        __syncthreads();  // previous O-phase done reading Ps/Vt (and Q visible)

        // Load K tile and transposed V tile
        #pragma unroll
        for (int f = tid; f < 64 * 32; f += 256) {
            int d = f >> 5, j4 = (f & 31) * 4;
            float4 kv = *(const float4*)(k + (size_t)d * SEQ + j0 + j4);
            *(float4*)&Ks[d * 128 + j4] = kv;
            float4 vv = *(const float4*)(v + (size_t)d * SEQ + j0 + j4);
            Vt[(j4 + 0) * 68 + d] = vv.x;
            Vt[(j4 + 1) * 68 + d] = vv.y;
            Vt[(j4 + 2) * 68 + d] = vv.z;
            Vt[(j4 + 3) * 68 + d] = vv.w;
        }
        __syncthreads();

        // S = Q^T K for this tile; thread computes 8x8 at (ty*8+a, tx+16*b)
        float s[8][8] = {};
        #pragma unroll 8
        for (int d = 0; d < 64; d++) {
            float4 q0 = *(float4*)&Qs[d * 128 + ty * 8];
            float4 q1 = *(float4*)&Qs[d * 128 + ty * 8 + 4];
            float qa[8] = {q0.x, q0.y, q0.z, q0.w, q1.x, q1.y, q1.z, q1.w};
            float kb[8];
            #pragma unroll
            for (int b = 0; b < 8; b++) kb[b] = Ks[d * 128 + tx + 16 * b];
            #pragma unroll
            for (int a = 0; a < 8; a++)
                #pragma unroll
                for (int b = 0; b < 8; b++)
                    s[a][b] = fmaf(qa[a], kb[b], s[a][b]);
        }

        // Online softmax update per owned row
        #pragma unroll
        for (int a = 0; a < 8; a++) {
            float mx = s[a][0];
            #pragma unroll
            for (int b = 1; b < 8; b++) mx = fmaxf(mx, s[a][b]);
            #pragma unroll
            for (int off = 8; off >= 1; off >>= 1)
                mx = fmaxf(mx, __shfl_xor_sync(0xffffffffu, mx, off));
            float mnew = fmaxf(mrow[a], mx);
            float alpha = __expf(mrow[a] - mnew);
            float rs = 0.0f;
            #pragma unroll
            for (int b = 0; b < 8; b++) {
                float p = __expf(s[a][b] - mnew);
                Ps[(ty * 8 + a) * 132 + tx + 16 * b] = p;
                rs += p;
            }
            #pragma unroll
            for (int off = 8; off >= 1; off >>= 1)
                rs += __shfl_xor_sync(0xffffffffu, rs, off);
            lrow[a] = lrow[a] * alpha + rs;
            mrow[a] = mnew;
            #pragma unroll
            for (int dd = 0; dd < 4; dd++) o[a][dd] *= alpha;
        }
        __syncthreads();  // Ps fully written

        // O += P * V^T ; thread owns rows ty*8+a, cols d = tx*4+dd
        #pragma unroll 4
        for (int jj = 0; jj < 128; jj += 4) {
            float4 vr[4];
            #pragma unroll
            for (int u = 0; u < 4; u++)
                vr[u] = *(float4*)&Vt[(jj + u) * 68 + tx * 4];
            #pragma unroll
            for (int a = 0; a < 8; a++) {
                float4 p4 = *(float4*)&Ps[(ty * 8 + a) * 132 + jj];
                o[a][0] = fmaf(p4.x, vr[0].x, o[a][0]);
                o[a][1] = fmaf(p4.x, vr[0].y, o[a][1]);
                o[a][2] = fmaf(p4.x, vr[0].z, o[a][2]);
                o[a][3] = fmaf(p4.x, vr[0].w, o[a][3]);
                o[a][0] = fmaf(p4.y, vr[1].x, o[a][0]);
                o[a][1] = fmaf(p4.y, vr[1].y, o[a][1]);
                o[a][2] = fmaf(p4.y, vr[1].z, o[a][2]);
                o[a][3] = fmaf(p4.y, vr[1].w, o[a][3]);
                o[a][0] = fmaf(p4.z, vr[2].x, o[a][0]);
                o[a][1] = fmaf(p4.z, vr[2].y, o[a][1]);
                o[a][2] = fmaf(p4.z, vr[2].z, o[a][2]);
                o[a][3] = fmaf(p4.z, vr[2].w, o[a][3]);
                o[a][0] = fmaf(p4.w, vr[3].x, o[a][0]);
                o[a][1] = fmaf(p4.w, vr[3].y, o[a][1]);
                o[a][2] = fmaf(p4.w, vr[3].z, o[a][2]);
                o[a][3] = fmaf(p4.w, vr[3].w, o[a][3]);
            }
        }
    }

    // Normalize and write out[h*64+d][i]
    #pragma unroll
    for (int a = 0; a < 8; a++) {
        float inv = 1.0f / lrow[a];
        #pragma unroll
        for (int dd = 0; dd < 4; dd++) {
            out[(size_t)(h * 64 + tx * 4 + dd) * SEQ + i0 + ty * 8 + a] =
                o[a][dd] * inv;
        }
    }
}

// ---------------------------------------------------------------------------
// Launch
// ---------------------------------------------------------------------------
extern "C" void kernel_launch(void* const* d_in, const int* in_sizes, int n_in,
                              void* d_out, int out_size)
{
    const float* x     = (const float*)d_in[0];   // [256][4096]
    const float* w_qkv = (const float*)d_in[1];   // [1536][256]
    const float* w_out = (const float*)d_in[2];   // [256][512]
    const float* b_out = (const float*)d_in[3];   // [256]
    float* out = (float*)d_out;                   // [256][4096]

    float* qkv_ptr = nullptr;
    float* att_ptr = nullptr;
    cudaGetSymbolAddress((void**)&qkv_ptr, g_qkv);
    cudaGetSymbolAddress((void**)&att_ptr, g_att);

    // 1) QKV projection: [1536,256] x [256,4096]
    gemm128x64<<<dim3(4096 / 64, 1536 / 128), 256>>>(
        w_qkv, x, nullptr, qkv_ptr, 1536, SEQ, 256);

    // 2) Flash attention
    const int smem_bytes = (2 * 64 * 128 + 128 * 68 + 128 * 132) * 4;  // 167936
    cudaFuncSetAttribute(flash_kernel,
                         cudaFuncAttributeMaxDynamicSharedMemorySize, smem_bytes);
    flash_kernel<<<dim3(SEQ / 128, NHEAD), 256, smem_bytes>>>(qkv_ptr, att_ptr);

    // 3) Output projection: [256,512] x [512,4096] + bias
    gemm128x64<<<dim3(4096 / 64, 256 / 128), 256>>>(
        w_out, att_ptr, b_out, out, 256, SEQ, 512);
}

// round 2
// speedup vs baseline: 2.6280x; 2.6280x over previous
#include <cuda_runtime.h>
#include <cuda_bf16.h>
#include <math.h>

#define SEQ   4096
#define NHEAD 8
#define DHEAD 64

__device__ float g_qkv[1536 * SEQ];
__device__ float g_att[512 * SEQ];

__device__ __forceinline__ float to_tf32(float x) {
    asm volatile("cvt.rna.tf32.f32 %0, %1;" : "=f"(x) : "f"(x));
    return x;
}

__device__ __forceinline__ void mma_tf32(float4& d, const float* a, float b0, float b1) {
    asm volatile(
        "mma.sync.aligned.m16n8k8.row.col.f32.tf32.tf32.f32 "
        "{%0,%1,%2,%3}, {%4,%5,%6,%7}, {%8,%9}, {%0,%1,%2,%3};"
        : "+f"(d.x), "+f"(d.y), "+f"(d.z), "+f"(d.w)
        : "r"(__float_as_uint(a[0])), "r"(__float_as_uint(a[1])),
          "r"(__float_as_uint(a[2])), "r"(__float_as_uint(a[3])),
          "r"(__float_as_uint(b0)), "r"(__float_as_uint(b1)));
}

// ---------------------------------------------------------------------------
// fp32 GEMM (unchanged): C[M,N] = A[M,K] * B[K,N] (+bias)
// ---------------------------------------------------------------------------
__global__ void __launch_bounds__(256) gemm128x64(
    const float* __restrict__ A, const float* __restrict__ B,
    const float* __restrict__ bias, float* __restrict__ C,
    int M, int N, int K)
{
    __shared__ __align__(16) float As[16][128];
    __shared__ __align__(16) float Bs[16][64];

    const int tid = threadIdx.x;
    const int ty = tid >> 4, tx = tid & 15;
    const int m0 = blockIdx.y * 128, n0 = blockIdx.x * 64;

    float acc[8][4] = {};

    for (int k0 = 0; k0 < K; k0 += 16) {
        #pragma unroll
        for (int i = 0; i < 2; i++) {
            int f = tid + i * 256;
            int r = f >> 2;
            int kq = (f & 3) * 4;
            float4 av = *(const float4*)(A + (size_t)(m0 + r) * K + k0 + kq);
            As[kq + 0][r] = av.x; As[kq + 1][r] = av.y;
            As[kq + 2][r] = av.z; As[kq + 3][r] = av.w;
        }
        {
            int kk = tid >> 4, n4 = (tid & 15) * 4;
            *(float4*)&Bs[kk][n4] =
                *(const float4*)(B + (size_t)(k0 + kk) * N + n0 + n4);
        }
        __syncthreads();

        #pragma unroll
        for (int kk = 0; kk < 16; kk++) {
            float4 a0 = *(float4*)&As[kk][ty * 8];
            float4 a1 = *(float4*)&As[kk][ty * 8 + 4];
            float4 b  = *(float4*)&Bs[kk][tx * 4];
            float ar[8] = {a0.x, a0.y, a0.z, a0.w, a1.x, a1.y, a1.z, a1.w};
            float br[4] = {b.x, b.y, b.z, b.w};
            #pragma unroll
            for (int a = 0; a < 8; a++)
                #pragma unroll
                for (int c = 0; c < 4; c++)
                    acc[a][c] = fmaf(ar[a], br[c], acc[a][c]);
        }
        __syncthreads();
    }

    #pragma unroll
    for (int a = 0; a < 8; a++) {
        int row = m0 + ty * 8 + a;
        float bb = bias ? bias[row] : 0.0f;
        float4 o = {acc[a][0] + bb, acc[a][1] + bb, acc[a][2] + bb, acc[a][3] + bb};
        *(float4*)(C + (size_t)row * N + n0 + tx * 4) = o;
    }
}

// ---------------------------------------------------------------------------
// Flash attention with tf32 mma.sync tensor cores.
// CTA = (head, 256 i-rows). 512 threads / 16 warps, warp w owns i-rows
// [16w, 16w+16). j-tiles of 64. m16n8k8 tf32, fp32 accumulate.
//
// SMEM: Ks[64 d][72] (d-major), Vs[64 j][72] (j-major), Ps[256 i][68].
// Pitches chosen conflict-free: 72 ≡ 8 (mod 32) for K/V B-frags,
// 68 ≡ 4 (mod 32) for P A-frags.
// ---------------------------------------------------------------------------
#define KP 72
#define PP 68

__global__ void __launch_bounds__(512, 1) flash_tc_kernel(float* __restrict__ out)
{
    extern __shared__ float sm[];
    float* Ks = sm;                    // 64*72
    float* Vs = sm + 64 * KP;          // 64*72
    float* Ps = sm + 2 * 64 * KP;      // 256*68

    const int tid  = threadIdx.x;
    const int lane = tid & 31;
    const int w    = tid >> 5;
    const int g    = lane >> 2;        // groupID 0..7
    const int t    = lane & 3;         // threadInGroup 0..3
    const int h    = blockIdx.y;
    const int i0   = blockIdx.x * 256;

    const float* qp = g_qkv + (size_t)(h * 64) * SEQ;
    const float* kp = g_qkv + (size_t)(512 + h * 64) * SEQ;
    const float* vp = g_qkv + (size_t)(1024 + h * 64) * SEQ;

    const float scale = 0.125f;
    const int iBase = i0 + w * 16;     // warp's absolute i start

    // Q fragments held in registers: qf[kd] covers k-cols d = 8kd..8kd+7.
    // a0:(row g, col t) a1:(row g+8, col t) a2:(row g, col t+4) a3:(row g+8, col t+4)
    float qf[8][4];
    #pragma unroll
    for (int kd = 0; kd < 8; kd++) {
        int d0 = 8 * kd + t;
        qf[kd][0] = to_tf32(qp[(size_t)(d0    ) * SEQ + iBase + g    ] * scale);
        qf[kd][1] = to_tf32(qp[(size_t)(d0    ) * SEQ + iBase + g + 8] * scale);
        qf[kd][2] = to_tf32(qp[(size_t)(d0 + 4) * SEQ + iBase + g    ] * scale);
        qf[kd][3] = to_tf32(qp[(size_t)(d0 + 4) * SEQ + iBase + g + 8] * scale);
    }

    float4 ob[8];
    #pragma unroll
    for (int nd = 0; nd < 8; nd++) ob[nd] = make_float4(0.f, 0.f, 0.f, 0.f);
    float m0 = -1e30f, m1 = -1e30f, l0 = 0.f, l1 = 0.f;

    for (int jt = 0; jt < 64; jt++) {
        const int j0 = jt * 64;

        // Stage K/V tile loads into regs (issue LDG before the barrier)
        float4 kv[2], vv[2];
        int dd[2], jj[2];
        #pragma unroll
        for (int u = 0; u < 2; u++) {
            int s = tid + u * 512;          // 0..1023 float4 slots
            dd[u] = s >> 4;
            jj[u] = (s & 15) << 2;
            kv[u] = *(const float4*)(kp + (size_t)dd[u] * SEQ + j0 + jj[u]);
            vv[u] = *(const float4*)(vp + (size_t)dd[u] * SEQ + j0 + jj[u]);
        }

        __syncthreads();  // prior iter done reading Ks/Vs

        #pragma unroll
        for (int u = 0; u < 2; u++) {
            float4 kc;
            kc.x = to_tf32(kv[u].x); kc.y = to_tf32(kv[u].y);
            kc.z = to_tf32(kv[u].z); kc.w = to_tf32(kv[u].w);
            *(float4*)&Ks[dd[u] * KP + jj[u]] = kc;
            Vs[(jj[u] + 0) * KP + dd[u]] = to_tf32(vv[u].x);
            Vs[(jj[u] + 1) * KP + dd[u]] = to_tf32(vv[u].y);
            Vs[(jj[u] + 2) * KP + dd[u]] = to_tf32(vv[u].z);
            Vs[(jj[u] + 3) * KP + dd[u]] = to_tf32(vv[u].w);
        }
        __syncthreads();

        // ---- S = Q^T K  (16 x 64 per warp) ----
        float4 sb[8];
        #pragma unroll
        for (int nj = 0; nj < 8; nj++) sb[nj] = make_float4(0.f, 0.f, 0.f, 0.f);

        #pragma unroll
        for (int kd = 0; kd < 8; kd++) {
            const int r0 = (8 * kd + t) * KP;
            const int r1 = (8 * kd + t + 4) * KP;
            #pragma unroll
            for (int nj = 0; nj < 8; nj++) {
                float b0 = Ks[r0 + 8 * nj + g];
                float b1 = Ks[r1 + 8 * nj + g];
                mma_tf32(sb[nj], qf[kd], b0, b1);
            }
        }

        // ---- online softmax on rows g (x,y regs) and g+8 (z,w regs) ----
        float mx0 = -1e30f, mx1 = -1e30f;
        #pragma unroll
        for (int nj = 0; nj < 8; nj++) {
            mx0 = fmaxf(mx0, fmaxf(sb[nj].x, sb[nj].y));
            mx1 = fmaxf(mx1, fmaxf(sb[nj].z, sb[nj].w));
        }
        mx0 = fmaxf(mx0, __shfl_xor_sync(0xffffffffu, mx0, 1));
        mx0 = fmaxf(mx0, __shfl_xor_sync(0xffffffffu, mx0, 2));
        mx1 = fmaxf(mx1, __shfl_xor_sync(0xffffffffu, mx1, 1));
        mx1 = fmaxf(mx1, __shfl_xor_sync(0xffffffffu, mx1, 2));

        float mn0 = fmaxf(m0, mx0), mn1 = fmaxf(m1, mx1);
        float al0 = __expf(m0 - mn0), al1 = __expf(m1 - mn1);
        m0 = mn0; m1 = mn1;

        float rs0 = 0.f, rs1 = 0.f;
        const int prow0 = (w * 16 + g) * PP;
        const int prow1 = prow0 + 8 * PP;
        #pragma unroll
        for (int nj = 0; nj < 8; nj++) {
            float ex = __expf(sb[nj].x - mn0);
            float ey = __expf(sb[nj].y - mn0);
            float ez = __expf(sb[nj].z - mn1);
            float ew = __expf(sb[nj].w - mn1);
            rs0 += ex + ey; rs1 += ez + ew;
            float2 p01 = make_float2(to_tf32(ex), to_tf32(ey));
            float2 p23 = make_float2(to_tf32(ez), to_tf32(ew));
            *(float2*)&Ps[prow0 + 8 * nj + 2 * t] = p01;
            *(float2*)&Ps[prow1 + 8 * nj + 2 * t] = p23;
        }
        rs0 += __shfl_xor_sync(0xffffffffu, rs0, 1);
        rs0 += __shfl_xor_sync(0xffffffffu, rs0, 2);
        rs1 += __shfl_xor_sync(0xffffffffu, rs1, 1);
        rs1 += __shfl_xor_sync(0xffffffffu, rs1, 2);
        l0 = l0 * al0 + rs0;
        l1 = l1 * al1 + rs1;

        #pragma unroll
        for (int nd = 0; nd < 8; nd++) {
            ob[nd].x *= al0; ob[nd].y *= al0;
            ob[nd].z *= al1; ob[nd].w *= al1;
        }

        __syncwarp();  // Ps rows are warp-private: warp-level visibility suffices

        // ---- O += P * V  (16 x 64 per warp) ----
        #pragma unroll
        for (int kk = 0; kk < 8; kk++) {
            float pa[4];
            pa[0] = Ps[prow0 + 8 * kk + t];
            pa[1] = Ps[prow1 + 8 * kk + t];
            pa[2] = Ps[prow0 + 8 * kk + t + 4];
            pa[3] = Ps[prow1 + 8 * kk + t + 4];
            const int r0 = (8 * kk + t) * KP;
            const int r1 = (8 * kk + t + 4) * KP;
            #pragma unroll
            for (int nd = 0; nd < 8; nd++) {
                float b0 = Vs[r0 + 8 * nd + g];
                float b1 = Vs[r1 + 8 * nd + g];
                mma_tf32(ob[nd], pa, b0, b1);
            }
        }
        __syncwarp();  // done reading Ps before next iter's softmax overwrites
    }

    // Normalize + write out[h*64 + d][i]
    float inv0 = 1.0f / l0, inv1 = 1.0f / l1;
    #pragma unroll
    for (int nd = 0; nd < 8; nd++) {
        int dcol = 8 * nd + 2 * t;
        out[(size_t)(h * 64 + dcol    ) * SEQ + iBase + g    ] = ob[nd].x * inv0;
        out[(size_t)(h * 64 + dcol + 1) * SEQ + iBase + g    ] = ob[nd].y * inv0;
        out[(size_t)(h * 64 + dcol    ) * SEQ + iBase + g + 8] = ob[nd].z * inv1;
        out[(size_t)(h * 64 + dcol + 1) * SEQ + iBase + g + 8] = ob[nd].w * inv1;
    }
}

// ---------------------------------------------------------------------------
extern "C" void kernel_launch(void* const* d_in, const int* in_sizes, int n_in,
                              void* d_out, int out_size)
{
    const float* x     = (const float*)d_in[0];
    const float* w_qkv = (const float*)d_in[1];
    const float* w_out = (const float*)d_in[2];
    const float* b_out = (const float*)d_in[3];
    float* out = (float*)d_out;

    float* qkv_ptr = nullptr;
    float* att_ptr = nullptr;
    cudaGetSymbolAddress((void**)&qkv_ptr, g_qkv);
    cudaGetSymbolAddress((void**)&att_ptr, g_att);

    // 1) QKV projection
    gemm128x64<<<dim3(4096 / 64, 1536 / 128), 256>>>(
        w_qkv, x, nullptr, qkv_ptr, 1536, SEQ, 256);

    // 2) Flash attention (tensor cores)
    const int smem_bytes = (2 * 64 * KP + 256 * PP) * 4;  // 106496
    cudaFuncSetAttribute(flash_tc_kernel,
                         cudaFuncAttributeMaxDynamicSharedMemorySize, smem_bytes);
    flash_tc_kernel<<<dim3(16, NHEAD), 512, smem_bytes>>>(att_ptr);

    // 3) Output projection + bias
    gemm128x64<<<dim3(4096 / 64, 256 / 128), 256>>>(
        w_out, att_ptr, b_out, out, 256, SEQ, 512);
}

// round 3
// speedup vs baseline: 3.7428x; 1.4242x over previous
#include <cuda_runtime.h>
#include <cuda_bf16.h>
#include <math.h>

#define SEQ   4096
#define NHEAD 8
#define DHEAD 64

__device__ float g_qkv[1536 * SEQ];
__device__ float g_att[512 * SEQ];

__device__ __forceinline__ float to_tf32(float x) {
    asm volatile("cvt.rna.tf32.f32 %0, %1;" : "=f"(x) : "f"(x));
    return x;
}

__device__ __forceinline__ void mma_tf32(float4& d, const float* a, float b0, float b1) {
    asm volatile(
        "mma.sync.aligned.m16n8k8.row.col.f32.tf32.tf32.f32 "
        "{%0,%1,%2,%3}, {%4,%5,%6,%7}, {%8,%9}, {%0,%1,%2,%3};"
        : "+f"(d.x), "+f"(d.y), "+f"(d.z), "+f"(d.w)
        : "r"(__float_as_uint(a[0])), "r"(__float_as_uint(a[1])),
          "r"(__float_as_uint(a[2])), "r"(__float_as_uint(a[3])),
          "r"(__float_as_uint(b0)), "r"(__float_as_uint(b1)));
}

// ---------------------------------------------------------------------------
// tf32 tensor-core GEMM: C[M,N] = A[M,K] * B[K,N] (+bias), row-major.
// CTA 128x128, 8 warps, warp tile 32x64 (2 m16 tiles x 8 n8 tiles), k-chunk 32.
// As m-major pitch 36 (bank 4g+t unique); Bs k-major pitch 136 (bank 8t+g).
// ---------------------------------------------------------------------------
#define GAP 36
#define GBP 136

__global__ void __launch_bounds__(256) gemm_tf32(
    const float* __restrict__ A, const float* __restrict__ B,
    const float* __restrict__ bias, float* __restrict__ C,
    int M, int N, int K)
{
    __shared__ __align__(16) float As[128 * GAP];
    __shared__ __align__(16) float Bs[32 * GBP];

    const int tid  = threadIdx.x;
    const int lane = tid & 31;
    const int w    = tid >> 5;
    const int g    = lane >> 2;
    const int t    = lane & 3;
    const int mb   = (w >> 1) * 32;
    const int nb   = (w & 1) * 64;
    const int m0   = blockIdx.y * 128, n0 = blockIdx.x * 128;

    float4 acc[2][8];
    #pragma unroll
    for (int mt = 0; mt < 2; mt++)
        #pragma unroll
        for (int nj = 0; nj < 8; nj++) acc[mt][nj] = make_float4(0.f, 0.f, 0.f, 0.f);

    for (int k0 = 0; k0 < K; k0 += 32) {
        float4 av[4], bv[4];
        int ar[4], ak[4], bk[4], bn[4];
        #pragma unroll
        for (int u = 0; u < 4; u++) {
            int s = tid + u * 256;
            ar[u] = s >> 3; ak[u] = (s & 7) * 4;
            av[u] = *(const float4*)(A + (size_t)(m0 + ar[u]) * K + k0 + ak[u]);
            bk[u] = s >> 5; bn[u] = (s & 31) * 4;
            bv[u] = *(const float4*)(B + (size_t)(k0 + bk[u]) * N + n0 + bn[u]);
        }
        __syncthreads();
        #pragma unroll
        for (int u = 0; u < 4; u++) {
            float4 ac, bc;
            ac.x = to_tf32(av[u].x); ac.y = to_tf32(av[u].y);
            ac.z = to_tf32(av[u].z); ac.w = to_tf32(av[u].w);
            *(float4*)&As[ar[u] * GAP + ak[u]] = ac;
            bc.x = to_tf32(bv[u].x); bc.y = to_tf32(bv[u].y);
            bc.z = to_tf32(bv[u].z); bc.w = to_tf32(bv[u].w);
            *(float4*)&Bs[bk[u] * GBP + bn[u]] = bc;
        }
        __syncthreads();

        #pragma unroll
        for (int kd = 0; kd < 4; kd++) {
            float af[2][4];
            #pragma unroll
            for (int mt = 0; mt < 2; mt++) {
                int r = mb + mt * 16;
                af[mt][0] = As[(r + g    ) * GAP + 8 * kd + t];
                af[mt][1] = As[(r + g + 8) * GAP + 8 * kd + t];
                af[mt][2] = As[(r + g    ) * GAP + 8 * kd + t + 4];
                af[mt][3] = As[(r + g + 8) * GAP + 8 * kd + t + 4];
            }
            const int r0 = (8 * kd + t) * GBP + nb;
            const int r1 = (8 * kd + t + 4) * GBP + nb;
            #pragma unroll
            for (int nj = 0; nj < 8; nj++) {
                float b0 = Bs[r0 + 8 * nj + g];
                float b1 = Bs[r1 + 8 * nj + g];
                mma_tf32(acc[0][nj], af[0], b0, b1);
                mma_tf32(acc[1][nj], af[1], b0, b1);
            }
        }
    }

    #pragma unroll
    for (int mt = 0; mt < 2; mt++) {
        int r0 = m0 + mb + mt * 16 + g;
        int r1 = r0 + 8;
        float bb0 = bias ? bias[r0] : 0.0f;
        float bb1 = bias ? bias[r1] : 0.0f;
        #pragma unroll
        for (int nj = 0; nj < 8; nj++) {
            int col = n0 + nb + 8 * nj + 2 * t;
            float2 lo = {acc[mt][nj].x + bb0, acc[mt][nj].y + bb0};
            float2 hi = {acc[mt][nj].z + bb1, acc[mt][nj].w + bb1};
            *(float2*)(C + (size_t)r0 * N + col) = lo;
            *(float2*)(C + (size_t)r1 * N + col) = hi;
        }
    }
}

// ---------------------------------------------------------------------------
// Flash attention tf32. CTA = (head, 256 rows), 8 warps, warp = 32 i-rows
// (2 m16 tiles sharing all B fragments). j-tile 64.
// Ks d-major pitch 72 (S B-frag bank 8t+g), Vs d-major pitch 68 (PV B-frag
// bank 4g+t) -- NO transpose, no conflicts. Ps pitch 68.
// ---------------------------------------------------------------------------
#define FKP 72
#define FVP 68
#define FPP 68

__global__ void __launch_bounds__(256, 1) flash_tc_kernel(float* __restrict__ out)
{
    extern __shared__ float sm[];
    float* Ks = sm;                       // 64*72
    float* Vs = sm + 64 * FKP;            // 64*68
    float* Ps = sm + 64 * FKP + 64 * FVP; // 256*68

    const int tid  = threadIdx.x;
    const int lane = tid & 31;
    const int w    = tid >> 5;
    const int g    = lane >> 2;
    const int t    = lane & 3;
    const int h    = blockIdx.y;
    const int iBase = blockIdx.x * 256 + w * 32;

    const float* qp = g_qkv + (size_t)(h * 64) * SEQ;
    const float* kp = g_qkv + (size_t)(512 + h * 64) * SEQ;
    const float* vp = g_qkv + (size_t)(1024 + h * 64) * SEQ;

    const float scale = 0.125f;

    // Q fragments: qf[mt][kd][*] for rows iBase+mt*16+{g,g+8}, cols 8kd+{t,t+4}
    float qf[2][8][4];
    #pragma unroll
    for (int mt = 0; mt < 2; mt++) {
        int I = iBase + mt * 16;
        #pragma unroll
        for (int kd = 0; kd < 8; kd++) {
            int d0 = 8 * kd + t;
            qf[mt][kd][0] = to_tf32(qp[(size_t)(d0    ) * SEQ + I + g    ] * scale);
            qf[mt][kd][1] = to_tf32(qp[(size_t)(d0    ) * SEQ + I + g + 8] * scale);
            qf[mt][kd][2] = to_tf32(qp[(size_t)(d0 + 4) * SEQ + I + g    ] * scale);
            qf[mt][kd][3] = to_tf32(qp[(size_t)(d0 + 4) * SEQ + I + g + 8] * scale);
        }
    }

    float4 ob[2][8];
    #pragma unroll
    for (int mt = 0; mt < 2; mt++)
        #pragma unroll
        for (int nd = 0; nd < 8; nd++) ob[mt][nd] = make_float4(0.f, 0.f, 0.f, 0.f);
    float mrow[2][2], lrow[2][2];
    #pragma unroll
    for (int mt = 0; mt < 2; mt++) {
        mrow[mt][0] = -1e30f; mrow[mt][1] = -1e30f;
        lrow[mt][0] = 0.f;    lrow[mt][1] = 0.f;
    }

    for (int jt = 0; jt < 64; jt++) {
        const int j0 = jt * 64;

        float4 kv[4], vv[4];
        int dd[4], jj[4];
        #pragma unroll
        for (int u = 0; u < 4; u++) {
            int s = tid + u * 256;
            dd[u] = s >> 4;
            jj[u] = (s & 15) << 2;
            kv[u] = *(const float4*)(kp + (size_t)dd[u] * SEQ + j0 + jj[u]);
            vv[u] = *(const float4*)(vp + (size_t)dd[u] * SEQ + j0 + jj[u]);
        }
        __syncthreads();  // prior iter done reading Ks/Vs
        #pragma unroll
        for (int u = 0; u < 4; u++) {
            float4 kc, vc;
            kc.x = to_tf32(kv[u].x); kc.y = to_tf32(kv[u].y);
            kc.z = to_tf32(kv[u].z); kc.w = to_tf32(kv[u].w);
            *(float4*)&Ks[dd[u] * FKP + jj[u]] = kc;
            vc.x = to_tf32(vv[u].x); vc.y = to_tf32(vv[u].y);
            vc.z = to_tf32(vv[u].z); vc.w = to_tf32(vv[u].w);
            *(float4*)&Vs[dd[u] * FVP + jj[u]] = vc;
        }
        __syncthreads();

        // ---- S = Q^T K : 32 x 64 per warp ----
        float4 sb[2][8];
        #pragma unroll
        for (int mt = 0; mt < 2; mt++)
            #pragma unroll
            for (int nj = 0; nj < 8; nj++) sb[mt][nj] = make_float4(0.f, 0.f, 0.f, 0.f);

        #pragma unroll
        for (int kd = 0; kd < 8; kd++) {
            const int r0 = (8 * kd + t) * FKP;
            const int r1 = (8 * kd + t + 4) * FKP;
            #pragma unroll
            for (int nj = 0; nj < 8; nj++) {
                float b0 = Ks[r0 + 8 * nj + g];
                float b1 = Ks[r1 + 8 * nj + g];
                mma_tf32(sb[0][nj], qf[0][kd], b0, b1);
                mma_tf32(sb[1][nj], qf[1][kd], b0, b1);
            }
        }

        // ---- online softmax (rows g: x,y | rows g+8: z,w) ----
        #pragma unroll
        for (int mt = 0; mt < 2; mt++) {
            float mx0 = -1e30f, mx1 = -1e30f;
            #pragma unroll
            for (int nj = 0; nj < 8; nj++) {
                mx0 = fmaxf(mx0, fmaxf(sb[mt][nj].x, sb[mt][nj].y));
                mx1 = fmaxf(mx1, fmaxf(sb[mt][nj].z, sb[mt][nj].w));
            }
            mx0 = fmaxf(mx0, __shfl_xor_sync(0xffffffffu, mx0, 1));
            mx0 = fmaxf(mx0, __shfl_xor_sync(0xffffffffu, mx0, 2));
            mx1 = fmaxf(mx1, __shfl_xor_sync(0xffffffffu, mx1, 1));
            mx1 = fmaxf(mx1, __shfl_xor_sync(0xffffffffu, mx1, 2));

            float mn0 = fmaxf(mrow[mt][0], mx0);
            float mn1 = fmaxf(mrow[mt][1], mx1);
            float al0 = __expf(mrow[mt][0] - mn0);
            float al1 = __expf(mrow[mt][1] - mn1);
            mrow[mt][0] = mn0; mrow[mt][1] = mn1;

            const int prow0 = (w * 32 + mt * 16 + g) * FPP;
            const int prow1 = prow0 + 8 * FPP;
            float rs0 = 0.f, rs1 = 0.f;
            #pragma unroll
            for (int nj = 0; nj < 8; nj++) {
                float ex = __expf(sb[mt][nj].x - mn0);
                float ey = __expf(sb[mt][nj].y - mn0);
                float ez = __expf(sb[mt][nj].z - mn1);
                float ew = __expf(sb[mt][nj].w - mn1);
                rs0 += ex + ey; rs1 += ez + ew;
                float2 p01 = make_float2(to_tf32(ex), to_tf32(ey));
                float2 p23 = make_float2(to_tf32(ez), to_tf32(ew));
                *(float2*)&Ps[prow0 + 8 * nj + 2 * t] = p01;
                *(float2*)&Ps[prow1 + 8 * nj + 2 * t] = p23;
            }
            rs0 += __shfl_xor_sync(0xffffffffu, rs0, 1);
            rs0 += __shfl_xor_sync(0xffffffffu, rs0, 2);
            rs1 += __shfl_xor_sync(0xffffffffu, rs1, 1);
            rs1 += __shfl_xor_sync(0xffffffffu, rs1, 2);
            lrow[mt][0] = lrow[mt][0] * al0 + rs0;
            lrow[mt][1] = lrow[mt][1] * al1 + rs1;
            #pragma unroll
            for (int nd = 0; nd < 8; nd++) {
                ob[mt][nd].x *= al0; ob[mt][nd].y *= al0;
                ob[mt][nd].z *= al1; ob[mt][nd].w *= al1;
            }
        }
        __syncwarp();  // Ps rows warp-private

        // ---- O += P * V : B-frag from d-major Vs ----
        #pragma unroll
        for (int kk = 0; kk < 8; kk++) {
            float pa[2][4];
            #pragma unroll
            for (int mt = 0; mt < 2; mt++) {
                const int pr = (w * 32 + mt * 16 + g) * FPP + 8 * kk;
                pa[mt][0] = Ps[pr + t];
                pa[mt][1] = Ps[pr + 8 * FPP + t];
                pa[mt][2] = Ps[pr + t + 4];
                pa[mt][3] = Ps[pr + 8 * FPP + t + 4];
            }
            #pragma unroll
            for (int nd = 0; nd < 8; nd++) {
                const int vr = (8 * nd + g) * FVP + 8 * kk;
                float b0 = Vs[vr + t];
                float b1 = Vs[vr + t + 4];
                mma_tf32(ob[0][nd], pa[0], b0, b1);
                mma_tf32(ob[1][nd], pa[1], b0, b1);
            }
        }
        __syncwarp();  // done reading Ps before next overwrite
    }

    #pragma unroll
    for (int mt = 0; mt < 2; mt++) {
        float inv0 = 1.0f / lrow[mt][0];
        float inv1 = 1.0f / lrow[mt][1];
        int I = iBase + mt * 16;
        #pragma unroll
        for (int nd = 0; nd < 8; nd++) {
            int dcol = 8 * nd + 2 * t;
            out[(size_t)(h * 64 + dcol    ) * SEQ + I + g    ] = ob[mt][nd].x * inv0;
            out[(size_t)(h * 64 + dcol + 1) * SEQ + I + g    ] = ob[mt][nd].y * inv0;
            out[(size_t)(h * 64 + dcol    ) * SEQ + I + g + 8] = ob[mt][nd].z * inv1;
            out[(size_t)(h * 64 + dcol + 1) * SEQ + I + g + 8] = ob[mt][nd].w * inv1;
        }
    }
}

// ---------------------------------------------------------------------------
extern "C" void kernel_launch(void* const* d_in, const int* in_sizes, int n_in,
                              void* d_out, int out_size)
{
    const float* x     = (const float*)d_in[0];
    const float* w_qkv = (const float*)d_in[1];
    const float* w_out = (const float*)d_in[2];
    const float* b_out = (const float*)d_in[3];
    float* out = (float*)d_out;

    float* qkv_ptr = nullptr;
    float* att_ptr = nullptr;
    cudaGetSymbolAddress((void**)&qkv_ptr, g_qkv);
    cudaGetSymbolAddress((void**)&att_ptr, g_att);

    // 1) QKV projection: [1536,256] x [256,4096]
    gemm_tf32<<<dim3(4096 / 128, 1536 / 128), 256>>>(
        w_qkv, x, nullptr, qkv_ptr, 1536, SEQ, 256);

    // 2) Flash attention
    const int smem_bytes = (64 * FKP + 64 * FVP + 256 * FPP) * 4;  // 105472
    cudaFuncSetAttribute(flash_tc_kernel,
                         cudaFuncAttributeMaxDynamicSharedMemorySize, smem_bytes);
    flash_tc_kernel<<<dim3(16, NHEAD), 256, smem_bytes>>>(att_ptr);

    // 3) Output projection + bias: [256,512] x [512,4096]
    gemm_tf32<<<dim3(4096 / 128, 256 / 128), 256>>>(
        w_out, att_ptr, b_out, out, 256, SEQ, 512);
}

// round 4
// speedup vs baseline: 3.8121x; 1.0185x over previous
#include <cuda_runtime.h>
#include <cuda_bf16.h>
#include <math.h>

#define SEQ   4096
#define NHEAD 8
#define DHEAD 64

__device__ float g_qkv[1536 * SEQ];
__device__ float g_att[512 * SEQ];

__device__ __forceinline__ float to_tf32(float x) {
    asm volatile("cvt.rna.tf32.f32 %0, %1;" : "=f"(x) : "f"(x));
    return x;
}
__device__ __forceinline__ float ex2(float x) {
    float r; asm("ex2.approx.f32 %0, %1;" : "=f"(r) : "f"(x)); return r;
}

__device__ __forceinline__ void mma_tf32(float4& d, const float* a, float b0, float b1) {
    asm volatile(
        "mma.sync.aligned.m16n8k8.row.col.f32.tf32.tf32.f32 "
        "{%0,%1,%2,%3}, {%4,%5,%6,%7}, {%8,%9}, {%0,%1,%2,%3};"
        : "+f"(d.x), "+f"(d.y), "+f"(d.z), "+f"(d.w)
        : "r"(__float_as_uint(a[0])), "r"(__float_as_uint(a[1])),
          "r"(__float_as_uint(a[2])), "r"(__float_as_uint(a[3])),
          "r"(__float_as_uint(b0)), "r"(__float_as_uint(b1)));
}

// ---------------------------------------------------------------------------
// tf32 tensor-core GEMM (unchanged from round 3)
// ---------------------------------------------------------------------------
#define GAP 36
#define GBP 136

__global__ void __launch_bounds__(256) gemm_tf32(
    const float* __restrict__ A, const float* __restrict__ B,
    const float* __restrict__ bias, float* __restrict__ C,
    int M, int N, int K)
{
    __shared__ __align__(16) float As[128 * GAP];
    __shared__ __align__(16) float Bs[32 * GBP];

    const int tid  = threadIdx.x;
    const int lane = tid & 31;
    const int w    = tid >> 5;
    const int g    = lane >> 2;
    const int t    = lane & 3;
    const int mb   = (w >> 1) * 32;
    const int nb   = (w & 1) * 64;
    const int m0   = blockIdx.y * 128, n0 = blockIdx.x * 128;

    float4 acc[2][8];
    #pragma unroll
    for (int mt = 0; mt < 2; mt++)
        #pragma unroll
        for (int nj = 0; nj < 8; nj++) acc[mt][nj] = make_float4(0.f, 0.f, 0.f, 0.f);

    for (int k0 = 0; k0 < K; k0 += 32) {
        float4 av[4], bv[4];
        int ar[4], ak[4], bk[4], bn[4];
        #pragma unroll
        for (int u = 0; u < 4; u++) {
            int s = tid + u * 256;
            ar[u] = s >> 3; ak[u] = (s & 7) * 4;
            av[u] = *(const float4*)(A + (size_t)(m0 + ar[u]) * K + k0 + ak[u]);
            bk[u] = s >> 5; bn[u] = (s & 31) * 4;
            bv[u] = *(const float4*)(B + (size_t)(k0 + bk[u]) * N + n0 + bn[u]);
        }
        __syncthreads();
        #pragma unroll
        for (int u = 0; u < 4; u++) {
            float4 ac, bc;
            ac.x = to_tf32(av[u].x); ac.y = to_tf32(av[u].y);
            ac.z = to_tf32(av[u].z); ac.w = to_tf32(av[u].w);
            *(float4*)&As[ar[u] * GAP + ak[u]] = ac;
            bc.x = to_tf32(bv[u].x); bc.y = to_tf32(bv[u].y);
            bc.z = to_tf32(bv[u].z); bc.w = to_tf32(bv[u].w);
            *(float4*)&Bs[bk[u] * GBP + bn[u]] = bc;
        }
        __syncthreads();

        #pragma unroll
        for (int kd = 0; kd < 4; kd++) {
            float af[2][4];
            #pragma unroll
            for (int mt = 0; mt < 2; mt++) {
                int r = mb + mt * 16;
                af[mt][0] = As[(r + g    ) * GAP + 8 * kd + t];
                af[mt][1] = As[(r + g + 8) * GAP + 8 * kd + t];
                af[mt][2] = As[(r + g    ) * GAP + 8 * kd + t + 4];
                af[mt][3] = As[(r + g + 8) * GAP + 8 * kd + t + 4];
            }
            const int r0 = (8 * kd + t) * GBP + nb;
            const int r1 = (8 * kd + t + 4) * GBP + nb;
            #pragma unroll
            for (int nj = 0; nj < 8; nj++) {
                float b0 = Bs[r0 + 8 * nj + g];
                float b1 = Bs[r1 + 8 * nj + g];
                mma_tf32(acc[0][nj], af[0], b0, b1);
                mma_tf32(acc[1][nj], af[1], b0, b1);
            }
        }
    }

    #pragma unroll
    for (int mt = 0; mt < 2; mt++) {
        int r0 = m0 + mb + mt * 16 + g;
        int r1 = r0 + 8;
        float bb0 = bias ? bias[r0] : 0.0f;
        float bb1 = bias ? bias[r1] : 0.0f;
        #pragma unroll
        for (int nj = 0; nj < 8; nj++) {
            int col = n0 + nb + 8 * nj + 2 * t;
            float2 lo = {acc[mt][nj].x + bb0, acc[mt][nj].y + bb0};
            float2 hi = {acc[mt][nj].z + bb1, acc[mt][nj].w + bb1};
            *(float2*)(C + (size_t)r0 * N + col) = lo;
            *(float2*)(C + (size_t)r1 * N + col) = hi;
        }
    }
}

// ---------------------------------------------------------------------------
// Flash attention tf32. CTA = (head, 128 rows), 4 warps, warp = 32 i-rows.
// 2 CTAs/SM for cross-CTA phase overlap. j-tile 64. exp in log2 domain.
// ---------------------------------------------------------------------------
#define FKP 72
#define FVP 68
#define FPP 68

__global__ void __launch_bounds__(128, 2) flash_tc_kernel(float* __restrict__ out)
{
    extern __shared__ float sm[];
    float* Ks = sm;                       // 64*72
    float* Vs = sm + 64 * FKP;            // 64*68
    float* Ps = sm + 64 * FKP + 64 * FVP; // 128*68

    const int tid  = threadIdx.x;
    const int lane = tid & 31;
    const int w    = tid >> 5;            // 0..3
    const int g    = lane >> 2;
    const int t    = lane & 3;
    const int h    = blockIdx.y;
    const int iBase = blockIdx.x * 128 + w * 32;

    const float* qp = g_qkv + (size_t)(h * 64) * SEQ;
    const float* kp = g_qkv + (size_t)(512 + h * 64) * SEQ;
    const float* vp = g_qkv + (size_t)(1024 + h * 64) * SEQ;

    const float scale = 0.125f * 1.44269504088896340736f;  // 1/8 * log2(e)

    float qf[2][8][4];
    #pragma unroll
    for (int mt = 0; mt < 2; mt++) {
        int I = iBase + mt * 16;
        #pragma unroll
        for (int kd = 0; kd < 8; kd++) {
            int d0 = 8 * kd + t;
            qf[mt][kd][0] = to_tf32(qp[(size_t)(d0    ) * SEQ + I + g    ] * scale);
            qf[mt][kd][1] = to_tf32(qp[(size_t)(d0    ) * SEQ + I + g + 8] * scale);
            qf[mt][kd][2] = to_tf32(qp[(size_t)(d0 + 4) * SEQ + I + g    ] * scale);
            qf[mt][kd][3] = to_tf32(qp[(size_t)(d0 + 4) * SEQ + I + g + 8] * scale);
        }
    }

    float4 ob[2][8];
    #pragma unroll
    for (int mt = 0; mt < 2; mt++)
        #pragma unroll
        for (int nd = 0; nd < 8; nd++) ob[mt][nd] = make_float4(0.f, 0.f, 0.f, 0.f);
    float mrow[2][2], lrow[2][2];
    #pragma unroll
    for (int mt = 0; mt < 2; mt++) {
        mrow[mt][0] = -1e30f; mrow[mt][1] = -1e30f;
        lrow[mt][0] = 0.f;    lrow[mt][1] = 0.f;
    }

    for (int jt = 0; jt < 64; jt++) {
        const int j0 = jt * 64;

        // Stage K/V tile (4096 elems each) via registers: 8 passes of float4.
        float4 kv[8], vv[8];
        int dd[8], jj[8];
        #pragma unroll
        for (int u = 0; u < 8; u++) {
            int s = tid + u * 128;
            dd[u] = s >> 4;
            jj[u] = (s & 15) << 2;
            kv[u] = *(const float4*)(kp + (size_t)dd[u] * SEQ + j0 + jj[u]);
            vv[u] = *(const float4*)(vp + (size_t)dd[u] * SEQ + j0 + jj[u]);
        }
        __syncthreads();
        #pragma unroll
        for (int u = 0; u < 8; u++) {
            float4 kc, vc;
            kc.x = to_tf32(kv[u].x); kc.y = to_tf32(kv[u].y);
            kc.z = to_tf32(kv[u].z); kc.w = to_tf32(kv[u].w);
            *(float4*)&Ks[dd[u] * FKP + jj[u]] = kc;
            vc.x = to_tf32(vv[u].x); vc.y = to_tf32(vv[u].y);
            vc.z = to_tf32(vv[u].z); vc.w = to_tf32(vv[u].w);
            *(float4*)&Vs[dd[u] * FVP + jj[u]] = vc;
        }
        __syncthreads();

        // ---- S = Q^T K : 32 x 64 per warp (scores already in log2 units) ----
        float4 sb[2][8];
        #pragma unroll
        for (int mt = 0; mt < 2; mt++)
            #pragma unroll
            for (int nj = 0; nj < 8; nj++) sb[mt][nj] = make_float4(0.f, 0.f, 0.f, 0.f);

        #pragma unroll
        for (int kd = 0; kd < 8; kd++) {
            const int r0 = (8 * kd + t) * FKP;
            const int r1 = (8 * kd + t + 4) * FKP;
            #pragma unroll
            for (int nj = 0; nj < 8; nj++) {
                float b0 = Ks[r0 + 8 * nj + g];
                float b1 = Ks[r1 + 8 * nj + g];
                mma_tf32(sb[0][nj], qf[0][kd], b0, b1);
                mma_tf32(sb[1][nj], qf[1][kd], b0, b1);
            }
        }

        // ---- online softmax in log2 domain ----
        #pragma unroll
        for (int mt = 0; mt < 2; mt++) {
            float mx0 = -1e30f, mx1 = -1e30f;
            #pragma unroll
            for (int nj = 0; nj < 8; nj++) {
                mx0 = fmaxf(mx0, fmaxf(sb[mt][nj].x, sb[mt][nj].y));
                mx1 = fmaxf(mx1, fmaxf(sb[mt][nj].z, sb[mt][nj].w));
            }
            mx0 = fmaxf(mx0, __shfl_xor_sync(0xffffffffu, mx0, 1));
            mx0 = fmaxf(mx0, __shfl_xor_sync(0xffffffffu, mx0, 2));
            mx1 = fmaxf(mx1, __shfl_xor_sync(0xffffffffu, mx1, 1));
            mx1 = fmaxf(mx1, __shfl_xor_sync(0xffffffffu, mx1, 2));

            float mn0 = fmaxf(mrow[mt][0], mx0);
            float mn1 = fmaxf(mrow[mt][1], mx1);
            float al0 = ex2(mrow[mt][0] - mn0);
            float al1 = ex2(mrow[mt][1] - mn1);
            mrow[mt][0] = mn0; mrow[mt][1] = mn1;

            const int prow0 = (w * 32 + mt * 16 + g) * FPP;
            const int prow1 = prow0 + 8 * FPP;
            float rs0 = 0.f, rs1 = 0.f;
            #pragma unroll
            for (int nj = 0; nj < 8; nj++) {
                float exv = ex2(sb[mt][nj].x - mn0);
                float eyv = ex2(sb[mt][nj].y - mn0);
                float ezv = ex2(sb[mt][nj].z - mn1);
                float ewv = ex2(sb[mt][nj].w - mn1);
                rs0 += exv + eyv; rs1 += ezv + ewv;
                float2 p01 = make_float2(to_tf32(exv), to_tf32(eyv));
                float2 p23 = make_float2(to_tf32(ezv), to_tf32(ewv));
                *(float2*)&Ps[prow0 + 8 * nj + 2 * t] = p01;
                *(float2*)&Ps[prow1 + 8 * nj + 2 * t] = p23;
            }
            rs0 += __shfl_xor_sync(0xffffffffu, rs0, 1);
            rs0 += __shfl_xor_sync(0xffffffffu, rs0, 2);
            rs1 += __shfl_xor_sync(0xffffffffu, rs1, 1);
            rs1 += __shfl_xor_sync(0xffffffffu, rs1, 2);
            lrow[mt][0] = lrow[mt][0] * al0 + rs0;
            lrow[mt][1] = lrow[mt][1] * al1 + rs1;
            #pragma unroll
            for (int nd = 0; nd < 8; nd++) {
                ob[mt][nd].x *= al0; ob[mt][nd].y *= al0;
                ob[mt][nd].z *= al1; ob[mt][nd].w *= al1;
            }
        }
        __syncwarp();  // Ps rows warp-private

        // ---- O += P * V ----
        #pragma unroll
        for (int kk = 0; kk < 8; kk++) {
            float pa[2][4];
            #pragma unroll
            for (int mt = 0; mt < 2; mt++) {
                const int pr = (w * 32 + mt * 16 + g) * FPP + 8 * kk;
                pa[mt][0] = Ps[pr + t];
                pa[mt][1] = Ps[pr + 8 * FPP + t];
                pa[mt][2] = Ps[pr + t + 4];
                pa[mt][3] = Ps[pr + 8 * FPP + t + 4];
            }
            #pragma unroll
            for (int nd = 0; nd < 8; nd++) {
                const int vr = (8 * nd + g) * FVP + 8 * kk;
                float b0 = Vs[vr + t];
                float b1 = Vs[vr + t + 4];
                mma_tf32(ob[0][nd], pa[0], b0, b1);
                mma_tf32(ob[1][nd], pa[1], b0, b1);
            }
        }
        __syncwarp();
    }

    #pragma unroll
    for (int mt = 0; mt < 2; mt++) {
        float inv0 = 1.0f / lrow[mt][0];
        float inv1 = 1.0f / lrow[mt][1];
        int I = iBase + mt * 16;
        #pragma unroll
        for (int nd = 0; nd < 8; nd++) {
            int dcol = 8 * nd + 2 * t;
            out[(size_t)(h * 64 + dcol    ) * SEQ + I + g    ] = ob[mt][nd].x * inv0;
            out[(size_t)(h * 64 + dcol + 1) * SEQ + I + g    ] = ob[mt][nd].y * inv0;
            out[(size_t)(h * 64 + dcol    ) * SEQ + I + g + 8] = ob[mt][nd].z * inv1;
            out[(size_t)(h * 64 + dcol + 1) * SEQ + I + g + 8] = ob[mt][nd].w * inv1;
        }
    }
}

// ---------------------------------------------------------------------------
extern "C" void kernel_launch(void* const* d_in, const int* in_sizes, int n_in,
                              void* d_out, int out_size)
{
    const float* x     = (const float*)d_in[0];
    const float* w_qkv = (const float*)d_in[1];
    const float* w_out = (const float*)d_in[2];
    const float* b_out = (const float*)d_in[3];
    float* out = (float*)d_out;

    float* qkv_ptr = nullptr;
    float* att_ptr = nullptr;
    cudaGetSymbolAddress((void**)&qkv_ptr, g_qkv);
    cudaGetSymbolAddress((void**)&att_ptr, g_att);

    // 1) QKV projection: [1536,256] x [256,4096]
    gemm_tf32<<<dim3(4096 / 128, 1536 / 128), 256>>>(
        w_qkv, x, nullptr, qkv_ptr, 1536, SEQ, 256);

    // 2) Flash attention: 256 CTAs, 2/SM
    const int smem_bytes = (64 * FKP + 64 * FVP + 128 * FPP) * 4;  // 70656
    cudaFuncSetAttribute(flash_tc_kernel,
                         cudaFuncAttributeMaxDynamicSharedMemorySize, smem_bytes);
    flash_tc_kernel<<<dim3(32, NHEAD), 128, smem_bytes>>>(att_ptr);

    // 3) Output projection + bias: [256,512] x [512,4096]
    gemm_tf32<<<dim3(4096 / 128, 256 / 128), 256>>>(
        w_out, att_ptr, b_out, out, 256, SEQ, 512);
}

// round 5
// speedup vs baseline: 6.1409x; 1.6109x over previous
#include <cuda_runtime.h>
#include <cuda_bf16.h>
#include <cuda_fp16.h>
#include <math.h>

#define SEQ   4096
#define NHEAD 8
#define DHEAD 64

__device__ float g_qkv[1536 * SEQ];
__device__ float g_att[512 * SEQ];

__device__ __forceinline__ float to_tf32(float x) {
    asm volatile("cvt.rna.tf32.f32 %0, %1;" : "=f"(x) : "f"(x));
    return x;
}
__device__ __forceinline__ float ex2(float x) {
    float r; asm("ex2.approx.f32 %0, %1;" : "=f"(r) : "f"(x)); return r;
}
// pack half2: low = lo, high = hi
__device__ __forceinline__ unsigned pack_h2(float lo, float hi) {
    unsigned d;
    asm("cvt.rn.f16x2.f32 %0, %1, %2;" : "=r"(d) : "f"(hi), "f"(lo));
    return d;
}

__device__ __forceinline__ void mma_tf32(float4& d, const float* a, float b0, float b1) {
    asm volatile(
        "mma.sync.aligned.m16n8k8.row.col.f32.tf32.tf32.f32 "
        "{%0,%1,%2,%3}, {%4,%5,%6,%7}, {%8,%9}, {%0,%1,%2,%3};"
        : "+f"(d.x), "+f"(d.y), "+f"(d.z), "+f"(d.w)
        : "r"(__float_as_uint(a[0])), "r"(__float_as_uint(a[1])),
          "r"(__float_as_uint(a[2])), "r"(__float_as_uint(a[3])),
          "r"(__float_as_uint(b0)), "r"(__float_as_uint(b1)));
}

__device__ __forceinline__ void mma_f16(float4& d, const unsigned* a,
                                        unsigned b0, unsigned b1) {
    asm volatile(
        "mma.sync.aligned.m16n8k16.row.col.f32.f16.f16.f32 "
        "{%0,%1,%2,%3}, {%4,%5,%6,%7}, {%8,%9}, {%0,%1,%2,%3};"
        : "+f"(d.x), "+f"(d.y), "+f"(d.z), "+f"(d.w)
        : "r"(a[0]), "r"(a[1]), "r"(a[2]), "r"(a[3]), "r"(b0), "r"(b1));
}

__device__ __forceinline__ void ldsm_x4(unsigned& r0, unsigned& r1,
                                        unsigned& r2, unsigned& r3, unsigned addr) {
    asm volatile("ldmatrix.sync.aligned.m8n8.x4.shared.b16 {%0,%1,%2,%3}, [%4];"
                 : "=r"(r0), "=r"(r1), "=r"(r2), "=r"(r3) : "r"(addr));
}
__device__ __forceinline__ void ldsm_x4_trans(unsigned& r0, unsigned& r1,
                                              unsigned& r2, unsigned& r3, unsigned addr) {
    asm volatile("ldmatrix.sync.aligned.m8n8.x4.trans.shared.b16 {%0,%1,%2,%3}, [%4];"
                 : "=r"(r0), "=r"(r1), "=r"(r2), "=r"(r3) : "r"(addr));
}

// ---------------------------------------------------------------------------
// tf32 tensor-core GEMM (unchanged)
// ---------------------------------------------------------------------------
#define GAP 36
#define GBP 136

__global__ void __launch_bounds__(256) gemm_tf32(
    const float* __restrict__ A, const float* __restrict__ B,
    const float* __restrict__ bias, float* __restrict__ C,
    int M, int N, int K)
{
    __shared__ __align__(16) float As[128 * GAP];
    __shared__ __align__(16) float Bs[32 * GBP];

    const int tid  = threadIdx.x;
    const int lane = tid & 31;
    const int w    = tid >> 5;
    const int g    = lane >> 2;
    const int t    = lane & 3;
    const int mb   = (w >> 1) * 32;
    const int nb   = (w & 1) * 64;
    const int m0   = blockIdx.y * 128, n0 = blockIdx.x * 128;

    float4 acc[2][8];
    #pragma unroll
    for (int mt = 0; mt < 2; mt++)
        #pragma unroll
        for (int nj = 0; nj < 8; nj++) acc[mt][nj] = make_float4(0.f, 0.f, 0.f, 0.f);

    for (int k0 = 0; k0 < K; k0 += 32) {
        float4 av[4], bv[4];
        int ar[4], ak[4], bk[4], bn[4];
        #pragma unroll
        for (int u = 0; u < 4; u++) {
            int s = tid + u * 256;
            ar[u] = s >> 3; ak[u] = (s & 7) * 4;
            av[u] = *(const float4*)(A + (size_t)(m0 + ar[u]) * K + k0 + ak[u]);
            bk[u] = s >> 5; bn[u] = (s & 31) * 4;
            bv[u] = *(const float4*)(B + (size_t)(k0 + bk[u]) * N + n0 + bn[u]);
        }
        __syncthreads();
        #pragma unroll
        for (int u = 0; u < 4; u++) {
            float4 ac, bc;
            ac.x = to_tf32(av[u].x); ac.y = to_tf32(av[u].y);
            ac.z = to_tf32(av[u].z); ac.w = to_tf32(av[u].w);
            *(float4*)&As[ar[u] * GAP + ak[u]] = ac;
            bc.x = to_tf32(bv[u].x); bc.y = to_tf32(bv[u].y);
            bc.z = to_tf32(bv[u].z); bc.w = to_tf32(bv[u].w);
            *(float4*)&Bs[bk[u] * GBP + bn[u]] = bc;
        }
        __syncthreads();

        #pragma unroll
        for (int kd = 0; kd < 4; kd++) {
            float af[2][4];
            #pragma unroll
            for (int mt = 0; mt < 2; mt++) {
                int r = mb + mt * 16;
                af[mt][0] = As[(r + g    ) * GAP + 8 * kd + t];
                af[mt][1] = As[(r + g + 8) * GAP + 8 * kd + t];
                af[mt][2] = As[(r + g    ) * GAP + 8 * kd + t + 4];
                af[mt][3] = As[(r + g + 8) * GAP + 8 * kd + t + 4];
            }
            const int r0 = (8 * kd + t) * GBP + nb;
            const int r1 = (8 * kd + t + 4) * GBP + nb;
            #pragma unroll
            for (int nj = 0; nj < 8; nj++) {
                float b0 = Bs[r0 + 8 * nj + g];
                float b1 = Bs[r1 + 8 * nj + g];
                mma_tf32(acc[0][nj], af[0], b0, b1);
                mma_tf32(acc[1][nj], af[1], b0, b1);
            }
        }
    }

    #pragma unroll
    for (int mt = 0; mt < 2; mt++) {
        int r0 = m0 + mb + mt * 16 + g;
        int r1 = r0 + 8;
        float bb0 = bias ? bias[r0] : 0.0f;
        float bb1 = bias ? bias[r1] : 0.0f;
        #pragma unroll
        for (int nj = 0; nj < 8; nj++) {
            int col = n0 + nb + 8 * nj + 2 * t;
            float2 lo = {acc[mt][nj].x + bb0, acc[mt][nj].y + bb0};
            float2 hi = {acc[mt][nj].z + bb1, acc[mt][nj].w + bb1};
            *(float2*)(C + (size_t)r0 * N + col) = lo;
            *(float2*)(C + (size_t)r1 * N + col) = hi;
        }
    }
}

// ---------------------------------------------------------------------------
// Flash attention, fp16 m16n8k16, fp32 accumulate.
// CTA = (head, 128 rows), 4 warps, warp = 32 i-rows; j-tile 64; 2 CTAs/SM.
// K/V in smem as half, d-major, pitch 72 halves. B-frags via ldmatrix.x4
// (.trans for K, plain for V). P stays in registers (A-frag == C-frag layout).
// ---------------------------------------------------------------------------
#define KPH 72

__global__ void __launch_bounds__(128, 2) flash_fp16_kernel(float* __restrict__ out)
{
    __shared__ __align__(16) __half Ks[64 * KPH];
    __shared__ __align__(16) __half Vs[64 * KPH];

    const int tid  = threadIdx.x;
    const int lane = tid & 31;
    const int w    = tid >> 5;            // 0..3
    const int g    = lane >> 2;
    const int t    = lane & 3;
    const int h    = blockIdx.y;
    const int iBase = blockIdx.x * 128 + w * 32;

    const float* qp = g_qkv + (size_t)(h * 64) * SEQ;
    const float* kp = g_qkv + (size_t)(512 + h * 64) * SEQ;
    const float* vp = g_qkv + (size_t)(1024 + h * 64) * SEQ;

    const unsigned ks_base = (unsigned)__cvta_generic_to_shared(Ks);
    const unsigned vs_base = (unsigned)__cvta_generic_to_shared(Vs);

    const float scale = 0.125f * 1.44269504088896340736f;  // 1/8 * log2(e)

    // Q A-fragments (half2), one-time load: qf[mt][kc][0..3]
    // a0:(row g, d=16kc+2t,+1) a1:(row g+8, same) a2:(row g, d+8) a3:(row g+8, d+8)
    unsigned qf[2][4][4];
    #pragma unroll
    for (int mt = 0; mt < 2; mt++) {
        int I = iBase + mt * 16;
        #pragma unroll
        for (int kc = 0; kc < 4; kc++) {
            int d0 = 16 * kc + 2 * t;
            qf[mt][kc][0] = pack_h2(qp[(size_t)(d0    ) * SEQ + I + g] * scale,
                                    qp[(size_t)(d0 + 1) * SEQ + I + g] * scale);
            qf[mt][kc][1] = pack_h2(qp[(size_t)(d0    ) * SEQ + I + g + 8] * scale,
                                    qp[(size_t)(d0 + 1) * SEQ + I + g + 8] * scale);
            qf[mt][kc][2] = pack_h2(qp[(size_t)(d0 + 8) * SEQ + I + g] * scale,
                                    qp[(size_t)(d0 + 9) * SEQ + I + g] * scale);
            qf[mt][kc][3] = pack_h2(qp[(size_t)(d0 + 8) * SEQ + I + g + 8] * scale,
                                    qp[(size_t)(d0 + 9) * SEQ + I + g + 8] * scale);
        }
    }

    float4 ob[2][8];
    #pragma unroll
    for (int mt = 0; mt < 2; mt++)
        #pragma unroll
        for (int nd = 0; nd < 8; nd++) ob[mt][nd] = make_float4(0.f, 0.f, 0.f, 0.f);
    float mrow[2][2], lrow[2][2];
    #pragma unroll
    for (int mt = 0; mt < 2; mt++) {
        mrow[mt][0] = -1e30f; mrow[mt][1] = -1e30f;
        lrow[mt][0] = 0.f;    lrow[mt][1] = 0.f;
    }

    // ldmatrix lane-address components (loop-invariant)
    const int kRow = lane & 15;             // K: row within 16-d chunk
    const int kColSel = lane >> 4;          // K: nj pair member
    const int vRow = lane & 7;              // V: row within 8-d tile
    const int vTileSel = lane >> 4;         // V: nd pair member
    const int vColSel = (lane >> 3) & 1;    // V: j-chunk half (+8)

    for (int jt = 0; jt < 64; jt++) {
        const int j0 = jt * 64;

        // Stage K/V tiles (64 d x 64 j floats each) -> half smem
        float4 kv[8], vv[8];
        int dd[8], jj[8];
        #pragma unroll
        for (int u = 0; u < 8; u++) {
            int s = tid + u * 128;
            dd[u] = s >> 4;
            jj[u] = (s & 15) << 2;
            kv[u] = *(const float4*)(kp + (size_t)dd[u] * SEQ + j0 + jj[u]);
            vv[u] = *(const float4*)(vp + (size_t)dd[u] * SEQ + j0 + jj[u]);
        }
        __syncthreads();  // prior iter done reading Ks/Vs
        #pragma unroll
        for (int u = 0; u < 8; u++) {
            uint2 kpk, vpk;
            kpk.x = pack_h2(kv[u].x, kv[u].y);
            kpk.y = pack_h2(kv[u].z, kv[u].w);
            vpk.x = pack_h2(vv[u].x, vv[u].y);
            vpk.y = pack_h2(vv[u].z, vv[u].w);
            *(uint2*)&Ks[dd[u] * KPH + jj[u]] = kpk;
            *(uint2*)&Vs[dd[u] * KPH + jj[u]] = vpk;
        }
        __syncthreads();

        // ---- S = Q K^T : 32 x 64 per warp ----
        float4 sb[2][8];
        #pragma unroll
        for (int mt = 0; mt < 2; mt++)
            #pragma unroll
            for (int nj = 0; nj < 8; nj++) sb[mt][nj] = make_float4(0.f, 0.f, 0.f, 0.f);

        #pragma unroll
        for (int kc = 0; kc < 4; kc++) {
            #pragma unroll
            for (int njp = 0; njp < 4; njp++) {
                unsigned b0, b1, b2, b3;
                unsigned addr = ks_base +
                    ((16 * kc + kRow) * KPH + 8 * (2 * njp + kColSel)) * 2;
                ldsm_x4_trans(b0, b1, b2, b3, addr);
                mma_f16(sb[0][2 * njp    ], qf[0][kc], b0, b1);
                mma_f16(sb[1][2 * njp    ], qf[1][kc], b0, b1);
                mma_f16(sb[0][2 * njp + 1], qf[0][kc], b2, b3);
                mma_f16(sb[1][2 * njp + 1], qf[1][kc], b2, b3);
            }
        }

        // ---- online softmax (log2 domain); P -> half2 A-frags in regs ----
        unsigned pf[2][4][4];
        #pragma unroll
        for (int mt = 0; mt < 2; mt++) {
            float mx0 = -1e30f, mx1 = -1e30f;
            #pragma unroll
            for (int nj = 0; nj < 8; nj++) {
                mx0 = fmaxf(mx0, fmaxf(sb[mt][nj].x, sb[mt][nj].y));
                mx1 = fmaxf(mx1, fmaxf(sb[mt][nj].z, sb[mt][nj].w));
            }
            mx0 = fmaxf(mx0, __shfl_xor_sync(0xffffffffu, mx0, 1));
            mx0 = fmaxf(mx0, __shfl_xor_sync(0xffffffffu, mx0, 2));
            mx1 = fmaxf(mx1, __shfl_xor_sync(0xffffffffu, mx1, 1));
            mx1 = fmaxf(mx1, __shfl_xor_sync(0xffffffffu, mx1, 2));

            float mn0 = fmaxf(mrow[mt][0], mx0);
            float mn1 = fmaxf(mrow[mt][1], mx1);
            float al0 = ex2(mrow[mt][0] - mn0);
            float al1 = ex2(mrow[mt][1] - mn1);
            mrow[mt][0] = mn0; mrow[mt][1] = mn1;

            float rs0 = 0.f, rs1 = 0.f;
            #pragma unroll
            for (int nj = 0; nj < 8; nj++) {
                float exv = ex2(sb[mt][nj].x - mn0);
                float eyv = ex2(sb[mt][nj].y - mn0);
                float ezv = ex2(sb[mt][nj].z - mn1);
                float ewv = ex2(sb[mt][nj].w - mn1);
                rs0 += exv + eyv; rs1 += ezv + ewv;
                int kc = nj >> 1, base = (nj & 1) * 2;
                pf[mt][kc][base + 0] = pack_h2(exv, eyv);
                pf[mt][kc][base + 1] = pack_h2(ezv, ewv);
            }
            rs0 += __shfl_xor_sync(0xffffffffu, rs0, 1);
            rs0 += __shfl_xor_sync(0xffffffffu, rs0, 2);
            rs1 += __shfl_xor_sync(0xffffffffu, rs1, 1);
            rs1 += __shfl_xor_sync(0xffffffffu, rs1, 2);
            lrow[mt][0] = lrow[mt][0] * al0 + rs0;
            lrow[mt][1] = lrow[mt][1] * al1 + rs1;
            #pragma unroll
            for (int nd = 0; nd < 8; nd++) {
                ob[mt][nd].x *= al0; ob[mt][nd].y *= al0;
                ob[mt][nd].z *= al1; ob[mt][nd].w *= al1;
            }
        }

        // ---- O += P V : P A-frags straight from registers ----
        #pragma unroll
        for (int kc = 0; kc < 4; kc++) {
            #pragma unroll
            for (int ndp = 0; ndp < 4; ndp++) {
                unsigned b0, b1, b2, b3;
                unsigned addr = vs_base +
                    ((8 * (2 * ndp + vTileSel) + vRow) * KPH
                     + 16 * kc + vColSel * 8) * 2;
                ldsm_x4(b0, b1, b2, b3, addr);
                mma_f16(ob[0][2 * ndp    ], pf[0][kc], b0, b1);
                mma_f16(ob[1][2 * ndp    ], pf[1][kc], b0, b1);
                mma_f16(ob[0][2 * ndp + 1], pf[0][kc], b2, b3);
                mma_f16(ob[1][2 * ndp + 1], pf[1][kc], b2, b3);
            }
        }
    }

    // Normalize + write out[h*64 + d][i]
    #pragma unroll
    for (int mt = 0; mt < 2; mt++) {
        float inv0 = 1.0f / lrow[mt][0];
        float inv1 = 1.0f / lrow[mt][1];
        int I = iBase + mt * 16;
        #pragma unroll
        for (int nd = 0; nd < 8; nd++) {
            int dcol = 8 * nd + 2 * t;
            out[(size_t)(h * 64 + dcol    ) * SEQ + I + g    ] = ob[mt][nd].x * inv0;
            out[(size_t)(h * 64 + dcol + 1) * SEQ + I + g    ] = ob[mt][nd].y * inv0;
            out[(size_t)(h * 64 + dcol    ) * SEQ + I + g + 8] = ob[mt][nd].z * inv1;
            out[(size_t)(h * 64 + dcol + 1) * SEQ + I + g + 8] = ob[mt][nd].w * inv1;
        }
    }
}

// ---------------------------------------------------------------------------
extern "C" void kernel_launch(void* const* d_in, const int* in_sizes, int n_in,
                              void* d_out, int out_size)
{
    const float* x     = (const float*)d_in[0];
    const float* w_qkv = (const float*)d_in[1];
    const float* w_out = (const float*)d_in[2];
    const float* b_out = (const float*)d_in[3];
    float* out = (float*)d_out;

    float* qkv_ptr = nullptr;
    float* att_ptr = nullptr;
    cudaGetSymbolAddress((void**)&qkv_ptr, g_qkv);
    cudaGetSymbolAddress((void**)&att_ptr, g_att);

    // 1) QKV projection: [1536,256] x [256,4096]
    gemm_tf32<<<dim3(4096 / 128, 1536 / 128), 256>>>(
        w_qkv, x, nullptr, qkv_ptr, 1536, SEQ, 256);

    // 2) Flash attention (fp16 tensor cores, static smem)
    flash_fp16_kernel<<<dim3(32, NHEAD), 128>>>(att_ptr);

    // 3) Output projection + bias: [256,512] x [512,4096]
    gemm_tf32<<<dim3(4096 / 128, 256 / 128), 256>>>(
        w_out, att_ptr, b_out, out, 256, SEQ, 512);
}

// round 6
// speedup vs baseline: 7.0369x; 1.1459x over previous
#include <cuda_runtime.h>
#include <cuda_bf16.h>
#include <cuda_fp16.h>
#include <math.h>

#define SEQ   4096
#define NHEAD 8
#define DHEAD 64

__device__ __half g_qkv_h[1536 * SEQ];   // [3*512][4096] d-major, Q pre-scaled
__device__ __half g_att_h[512 * SEQ];    // [512][4096]   d-major

__device__ __forceinline__ float ex2(float x) {
    float r; asm("ex2.approx.f32 %0, %1;" : "=f"(r) : "f"(x)); return r;
}
__device__ __forceinline__ unsigned pack_h2(float lo, float hi) {
    unsigned d;
    asm("cvt.rn.f16x2.f32 %0, %1, %2;" : "=r"(d) : "f"(hi), "f"(lo));
    return d;
}

__device__ __forceinline__ void mma_f16(float4& d, const unsigned* a,
                                        unsigned b0, unsigned b1) {
    asm volatile(
        "mma.sync.aligned.m16n8k16.row.col.f32.f16.f16.f32 "
        "{%0,%1,%2,%3}, {%4,%5,%6,%7}, {%8,%9}, {%0,%1,%2,%3};"
        : "+f"(d.x), "+f"(d.y), "+f"(d.z), "+f"(d.w)
        : "r"(a[0]), "r"(a[1]), "r"(a[2]), "r"(a[3]), "r"(b0), "r"(b1));
}
__device__ __forceinline__ void ldsm_x4(unsigned& r0, unsigned& r1,
                                        unsigned& r2, unsigned& r3, unsigned addr) {
    asm volatile("ldmatrix.sync.aligned.m8n8.x4.shared.b16 {%0,%1,%2,%3}, [%4];"
                 : "=r"(r0), "=r"(r1), "=r"(r2), "=r"(r3) : "r"(addr));
}
__device__ __forceinline__ void ldsm_x4_trans(unsigned& r0, unsigned& r1,
                                              unsigned& r2, unsigned& r3, unsigned addr) {
    asm volatile("ldmatrix.sync.aligned.m8n8.x4.trans.shared.b16 {%0,%1,%2,%3}, [%4];"
                 : "=r"(r0), "=r"(r1), "=r"(r2), "=r"(r3) : "r"(addr));
}

// ---------------------------------------------------------------------------
// fp16 tensor-core GEMM: C[M,N] = A[M,K](fp32) * B[K,N] (+bias), row-major.
// CTA 128x128, 8 warps, warp tile 32x64, BK=32 (2 k16 chunks).
// B_HALF: B is fp16 (else fp32, converted). C_HALF: C is fp16; rows < scaleRows
// are multiplied by scaleQ before store (Q pre-scaling). Else C fp32 + bias.
// ---------------------------------------------------------------------------
#define AP 40    // As pitch (halves): 80B = 20 banks/row -> ldmatrix conflict-free
#define BP 136   // Bs pitch (halves): 272B = 4 banks/row -> ldmatrix conflict-free

template<bool B_HALF, bool C_HALF>
__global__ void __launch_bounds__(256) gemm_f16(
    const float* __restrict__ A, const void* __restrict__ Bv,
    const float* __restrict__ bias, void* __restrict__ Cv,
    int M, int N, int K, float scaleQ, int scaleRows)
{
    __shared__ __align__(16) __half As[128 * AP];
    __shared__ __align__(16) __half Bs[32 * BP];

    const int tid  = threadIdx.x;
    const int lane = tid & 31;
    const int w    = tid >> 5;
    const int g    = lane >> 2;
    const int t    = lane & 3;
    const int mb   = (w >> 1) * 32;
    const int nb   = (w & 1) * 64;
    const int m0   = blockIdx.y * 128, n0 = blockIdx.x * 128;

    const unsigned as_base = (unsigned)__cvta_generic_to_shared(As);
    const unsigned bs_base = (unsigned)__cvta_generic_to_shared(Bs);

    float4 acc[2][8];
    #pragma unroll
    for (int mt = 0; mt < 2; mt++)
        #pragma unroll
        for (int nj = 0; nj < 8; nj++) acc[mt][nj] = make_float4(0.f, 0.f, 0.f, 0.f);

    for (int k0 = 0; k0 < K; k0 += 32) {
        // Stage A (128x32 fp32 -> half)
        float4 av[4];
        int ar[4], ak[4];
        #pragma unroll
        for (int u = 0; u < 4; u++) {
            int s = tid + u * 256;
            ar[u] = s >> 3; ak[u] = (s & 7) * 4;
            av[u] = *(const float4*)(A + (size_t)(m0 + ar[u]) * K + k0 + ak[u]);
        }
        // Stage B
        uint4  bh[2];
        float4 bf[4];
        int bk[4], bn[4];
        if (B_HALF) {
            const __half* Bh = (const __half*)Bv;
            #pragma unroll
            for (int u = 0; u < 2; u++) {
                int s = tid + u * 256;
                bk[u] = s >> 4; bn[u] = (s & 15) * 8;
                bh[u] = *(const uint4*)(Bh + (size_t)(k0 + bk[u]) * N + n0 + bn[u]);
            }
        } else {
            const float* Bf = (const float*)Bv;
            #pragma unroll
            for (int u = 0; u < 4; u++) {
                int s = tid + u * 256;
                bk[u] = s >> 5; bn[u] = (s & 31) * 4;
                bf[u] = *(const float4*)(Bf + (size_t)(k0 + bk[u]) * N + n0 + bn[u]);
            }
        }
        __syncthreads();
        #pragma unroll
        for (int u = 0; u < 4; u++) {
            uint2 ap;
            ap.x = pack_h2(av[u].x, av[u].y);
            ap.y = pack_h2(av[u].z, av[u].w);
            *(uint2*)&As[ar[u] * AP + ak[u]] = ap;
        }
        if (B_HALF) {
            #pragma unroll
            for (int u = 0; u < 2; u++)
                *(uint4*)&Bs[bk[u] * BP + bn[u]] = bh[u];
        } else {
            #pragma unroll
            for (int u = 0; u < 4; u++) {
                uint2 bp;
                bp.x = pack_h2(bf[u].x, bf[u].y);
                bp.y = pack_h2(bf[u].z, bf[u].w);
                *(uint2*)&Bs[bk[u] * BP + bn[u]] = bp;
            }
        }
        __syncthreads();

        #pragma unroll
        for (int kc = 0; kc < 2; kc++) {
            unsigned af[2][4];
            #pragma unroll
            for (int mt = 0; mt < 2; mt++) {
                unsigned addr = as_base +
                    ((mb + mt * 16 + (lane & 15)) * AP + 16 * kc + 8 * (lane >> 4)) * 2;
                ldsm_x4(af[mt][0], af[mt][1], af[mt][2], af[mt][3], addr);
            }
            #pragma unroll
            for (int njp = 0; njp < 4; njp++) {
                unsigned b0, b1, b2, b3;
                unsigned addr = bs_base +
                    ((16 * kc + (lane & 15)) * BP + nb + 8 * (2 * njp + (lane >> 4))) * 2;
                ldsm_x4_trans(b0, b1, b2, b3, addr);
                mma_f16(acc[0][2 * njp    ], af[0], b0, b1);
                mma_f16(acc[1][2 * njp    ], af[1], b0, b1);
                mma_f16(acc[0][2 * njp + 1], af[0], b2, b3);
                mma_f16(acc[1][2 * njp + 1], af[1], b2, b3);
            }
        }
        __syncthreads();
    }

    #pragma unroll
    for (int mt = 0; mt < 2; mt++) {
        int r0 = m0 + mb + mt * 16 + g;
        int r1 = r0 + 8;
        if (C_HALF) {
            __half* Ch = (__half*)Cv;
            float sc0 = (r0 < scaleRows) ? scaleQ : 1.0f;
            float sc1 = (r1 < scaleRows) ? scaleQ : 1.0f;
            #pragma unroll
            for (int nj = 0; nj < 8; nj++) {
                int col = n0 + nb + 8 * nj + 2 * t;
                unsigned lo = pack_h2(acc[mt][nj].x * sc0, acc[mt][nj].y * sc0);
                unsigned hi = pack_h2(acc[mt][nj].z * sc1, acc[mt][nj].w * sc1);
                *(unsigned*)((__half*)Ch + (size_t)r0 * N + col) = lo;
                *(unsigned*)((__half*)Ch + (size_t)r1 * N + col) = hi;
            }
        } else {
            float* Cf = (float*)Cv;
            float bb0 = bias ? bias[r0] : 0.0f;
            float bb1 = bias ? bias[r1] : 0.0f;
            #pragma unroll
            for (int nj = 0; nj < 8; nj++) {
                int col = n0 + nb + 8 * nj + 2 * t;
                float2 lo = {acc[mt][nj].x + bb0, acc[mt][nj].y + bb0};
                float2 hi = {acc[mt][nj].z + bb1, acc[mt][nj].w + bb1};
                *(float2*)(Cf + (size_t)r0 * N + col) = lo;
                *(float2*)(Cf + (size_t)r1 * N + col) = hi;
            }
        }
    }
}

// ---------------------------------------------------------------------------
// Flash attention, fp16 m16n8k16, fp32 accumulate. Inputs/outputs fp16.
// CTA = (head, 128 rows), 4 warps, warp = 32 i-rows; j-tile 64; 2 CTAs/SM.
// Q pre-scaled by 0.125*log2(e) in the QKV GEMM. Output half -> g_att_h.
// ---------------------------------------------------------------------------
#define KPH 72

__global__ void __launch_bounds__(128, 2) flash_fp16_kernel()
{
    __shared__ __align__(16) __half Ks[64 * KPH];
    __shared__ __align__(16) __half Vs[64 * KPH];

    const int tid  = threadIdx.x;
    const int lane = tid & 31;
    const int w    = tid >> 5;
    const int g    = lane >> 2;
    const int t    = lane & 3;
    const int h    = blockIdx.y;
    const int iBase = blockIdx.x * 128 + w * 32;

    const __half* qp = g_qkv_h + (size_t)(h * 64) * SEQ;
    const __half* kp = g_qkv_h + (size_t)(512 + h * 64) * SEQ;
    const __half* vp = g_qkv_h + (size_t)(1024 + h * 64) * SEQ;

    const unsigned ks_base = (unsigned)__cvta_generic_to_shared(Ks);
    const unsigned vs_base = (unsigned)__cvta_generic_to_shared(Vs);

    // Q A-fragments: pre-scaled halves straight from global.
    unsigned qf[2][4][4];
    #pragma unroll
    for (int mt = 0; mt < 2; mt++) {
        int I = iBase + mt * 16;
        #pragma unroll
        for (int kc = 0; kc < 4; kc++) {
            int d0 = 16 * kc + 2 * t;
            #pragma unroll
            for (int r = 0; r < 4; r++) {
                int dv = d0 + (r >> 1) * 8;
                int iv = I + g + (r & 1) * 8;
                __half2 hh = __halves2half2(qp[(size_t)dv * SEQ + iv],
                                            qp[(size_t)(dv + 1) * SEQ + iv]);
                qf[mt][kc][r] = *(unsigned*)&hh;
            }
        }
    }

    float4 ob[2][8];
    #pragma unroll
    for (int mt = 0; mt < 2; mt++)
        #pragma unroll
        for (int nd = 0; nd < 8; nd++) ob[mt][nd] = make_float4(0.f, 0.f, 0.f, 0.f);
    float mrow[2][2], lrow[2][2];
    #pragma unroll
    for (int mt = 0; mt < 2; mt++) {
        mrow[mt][0] = -1e30f; mrow[mt][1] = -1e30f;
        lrow[mt][0] = 0.f;    lrow[mt][1] = 0.f;
    }

    const int kRow = lane & 15;
    const int kColSel = lane >> 4;
    const int vRow = lane & 7;
    const int vTileSel = lane >> 4;
    const int vColSel = (lane >> 3) & 1;

    for (int jt = 0; jt < 64; jt++) {
        const int j0 = jt * 64;

        // Stage K/V tiles: straight uint4 half copies (no conversion).
        uint4 kv4[4], vv4[4];
        int dd[4], jj[4];
        #pragma unroll
        for (int u = 0; u < 4; u++) {
            int s = tid + u * 128;
            dd[u] = s >> 3;
            jj[u] = (s & 7) * 8;
            kv4[u] = *(const uint4*)(kp + (size_t)dd[u] * SEQ + j0 + jj[u]);
            vv4[u] = *(const uint4*)(vp + (size_t)dd[u] * SEQ + j0 + jj[u]);
        }
        __syncthreads();
        #pragma unroll
        for (int u = 0; u < 4; u++) {
            *(uint4*)&Ks[dd[u] * KPH + jj[u]] = kv4[u];
            *(uint4*)&Vs[dd[u] * KPH + jj[u]] = vv4[u];
        }
        __syncthreads();

        // ---- S = Q K^T ----
        float4 sb[2][8];
        #pragma unroll
        for (int mt = 0; mt < 2; mt++)
            #pragma unroll
            for (int nj = 0; nj < 8; nj++) sb[mt][nj] = make_float4(0.f, 0.f, 0.f, 0.f);

        #pragma unroll
        for (int kc = 0; kc < 4; kc++) {
            #pragma unroll
            for (int njp = 0; njp < 4; njp++) {
                unsigned b0, b1, b2, b3;
                unsigned addr = ks_base +
                    ((16 * kc + kRow) * KPH + 8 * (2 * njp + kColSel)) * 2;
                ldsm_x4_trans(b0, b1, b2, b3, addr);
                mma_f16(sb[0][2 * njp    ], qf[0][kc], b0, b1);
                mma_f16(sb[1][2 * njp    ], qf[1][kc], b0, b1);
                mma_f16(sb[0][2 * njp + 1], qf[0][kc], b2, b3);
                mma_f16(sb[1][2 * njp + 1], qf[1][kc], b2, b3);
            }
        }

        // ---- online softmax (log2 domain) ----
        unsigned pf[2][4][4];
        #pragma unroll
        for (int mt = 0; mt < 2; mt++) {
            float mx0 = -1e30f, mx1 = -1e30f;
            #pragma unroll
            for (int nj = 0; nj < 8; nj++) {
                mx0 = fmaxf(mx0, fmaxf(sb[mt][nj].x, sb[mt][nj].y));
                mx1 = fmaxf(mx1, fmaxf(sb[mt][nj].z, sb[mt][nj].w));
            }
            mx0 = fmaxf(mx0, __shfl_xor_sync(0xffffffffu, mx0, 1));
            mx0 = fmaxf(mx0, __shfl_xor_sync(0xffffffffu, mx0, 2));
            mx1 = fmaxf(mx1, __shfl_xor_sync(0xffffffffu, mx1, 1));
            mx1 = fmaxf(mx1, __shfl_xor_sync(0xffffffffu, mx1, 2));

            float mn0 = fmaxf(mrow[mt][0], mx0);
            float mn1 = fmaxf(mrow[mt][1], mx1);
            float al0 = ex2(mrow[mt][0] - mn0);
            float al1 = ex2(mrow[mt][1] - mn1);
            mrow[mt][0] = mn0; mrow[mt][1] = mn1;

            float rs0 = 0.f, rs1 = 0.f;
            #pragma unroll
            for (int nj = 0; nj < 8; nj++) {
                float exv = ex2(sb[mt][nj].x - mn0);
                float eyv = ex2(sb[mt][nj].y - mn0);
                float ezv = ex2(sb[mt][nj].z - mn1);
                float ewv = ex2(sb[mt][nj].w - mn1);
                rs0 += exv + eyv; rs1 += ezv + ewv;
                int kc = nj >> 1, base = (nj & 1) * 2;
                pf[mt][kc][base + 0] = pack_h2(exv, eyv);
                pf[mt][kc][base + 1] = pack_h2(ezv, ewv);
            }
            rs0 += __shfl_xor_sync(0xffffffffu, rs0, 1);
            rs0 += __shfl_xor_sync(0xffffffffu, rs0, 2);
            rs1 += __shfl_xor_sync(0xffffffffu, rs1, 1);
            rs1 += __shfl_xor_sync(0xffffffffu, rs1, 2);
            lrow[mt][0] = lrow[mt][0] * al0 + rs0;
            lrow[mt][1] = lrow[mt][1] * al1 + rs1;
            #pragma unroll
            for (int nd = 0; nd < 8; nd++) {
                ob[mt][nd].x *= al0; ob[mt][nd].y *= al0;
                ob[mt][nd].z *= al1; ob[mt][nd].w *= al1;
            }
        }

        // ---- O += P V ----
        #pragma unroll
        for (int kc = 0; kc < 4; kc++) {
            #pragma unroll
            for (int ndp = 0; ndp < 4; ndp++) {
                unsigned b0, b1, b2, b3;
                unsigned addr = vs_base +
                    ((8 * (2 * ndp + vTileSel) + vRow) * KPH
                     + 16 * kc + vColSel * 8) * 2;
                ldsm_x4(b0, b1, b2, b3, addr);
                mma_f16(ob[0][2 * ndp    ], pf[0][kc], b0, b1);
                mma_f16(ob[1][2 * ndp    ], pf[1][kc], b0, b1);
                mma_f16(ob[0][2 * ndp + 1], pf[0][kc], b2, b3);
                mma_f16(ob[1][2 * ndp + 1], pf[1][kc], b2, b3);
            }
        }
    }

    // Normalize and write half output (d-major)
    __half* op = g_att_h + (size_t)(h * 64) * SEQ;
    #pragma unroll
    for (int mt = 0; mt < 2; mt++) {
        float inv0 = 1.0f / lrow[mt][0];
        float inv1 = 1.0f / lrow[mt][1];
        int I = iBase + mt * 16;
        #pragma unroll
        for (int nd = 0; nd < 8; nd++) {
            int dcol = 8 * nd + 2 * t;
            op[(size_t)(dcol    ) * SEQ + I + g    ] = __float2half(ob[mt][nd].x * inv0);
            op[(size_t)(dcol + 1) * SEQ + I + g    ] = __float2half(ob[mt][nd].y * inv0);
            op[(size_t)(dcol    ) * SEQ + I + g + 8] = __float2half(ob[mt][nd].z * inv1);
            op[(size_t)(dcol + 1) * SEQ + I + g + 8] = __float2half(ob[mt][nd].w * inv1);
        }
    }
}

// ---------------------------------------------------------------------------
extern "C" void kernel_launch(void* const* d_in, const int* in_sizes, int n_in,
                              void* d_out, int out_size)
{
    const float* x     = (const float*)d_in[0];
    const float* w_qkv = (const float*)d_in[1];
    const float* w_out = (const float*)d_in[2];
    const float* b_out = (const float*)d_in[3];
    float* out = (float*)d_out;

    __half* qkv_ptr = nullptr;
    __half* att_ptr = nullptr;
    cudaGetSymbolAddress((void**)&qkv_ptr, g_qkv_h);
    cudaGetSymbolAddress((void**)&att_ptr, g_att_h);

    const float qscale = 0.125f * 1.44269504088896340736f;  // 1/8 * log2(e)

    // 1) QKV projection -> fp16 scratch, Q rows pre-scaled
    gemm_f16<false, true><<<dim3(4096 / 128, 1536 / 128), 256>>>(
        w_qkv, x, nullptr, qkv_ptr, 1536, SEQ, 256, qscale, 512);

    // 2) Flash attention (fp16 in/out)
    flash_fp16_kernel<<<dim3(32, NHEAD), 128>>>();

    // 3) Output projection (fp16 B) + bias -> fp32 out
    gemm_f16<true, false><<<dim3(4096 / 128, 256 / 128), 256>>>(
        w_out, att_ptr, b_out, out, 256, SEQ, 512, 1.0f, 0);
}